// round 9
// baseline (speedup 1.0000x reference)
#include <cuda_runtime.h>
#include <cstdint>
#include <cstddef>

// Shapes
#define BATCH   8
#define SEQ     4096
#define CDIM    768
#define EDIM    768
#define MTOK    (BATCH*SEQ)      // 32768
#define QKVCOLS (3*EDIM)         // 2304

// ---------------- scratch ----------------
__device__ float g_qkv[(size_t)MTOK * QKVCOLS];      // 302 MB (tf32-rounded)
__device__ float g_xr[(size_t)MTOK * CDIM];          // 96 MB tf32-rounded x
__device__ float g_wgt[(size_t)QKVCOLS * CDIM];      // WgT[n][k] 7 MB
__device__ float g_wbt[(size_t)BATCH * EDIM * EDIM]; // WbT[b][n][e] 19 MB
__device__ float g_s1[QKVCOLS];
__device__ float g_s2[QKVCOLS];
__device__ float g_t1[CDIM];
__device__ float g_t2[CDIM];
__device__ float g_alpha1[MTOK];
__device__ float g_beta1[MTOK];
__device__ float g_alpha2[MTOK];
__device__ float g_beta2[MTOK];
__device__ float g_invnk[MTOK];
__device__ float g_kv[BATCH * EDIM];

// ---------------- helpers ----------------
__device__ __forceinline__ float wsum(float v) {
#pragma unroll
    for (int o = 16; o > 0; o >>= 1) v += __shfl_xor_sync(0xFFFFFFFFu, v, o);
    return v;
}
__device__ __forceinline__ float tf32f(float x) {
    uint32_t u;
    asm("cvt.rna.tf32.f32 %0, %1;" : "=r"(u) : "f"(x));
    return __uint_as_float(u);
}
__device__ __forceinline__ uint32_t smem_u32(const void* p) {
    uint32_t a;
    asm("{ .reg .u64 t; cvta.to.shared.u64 t, %1; cvt.u32.u64 %0, t; }" : "=r"(a) : "l"(p));
    return a;
}
__device__ __forceinline__ void cpasync16(uint32_t s, const void* g) {
    asm volatile("cp.async.cg.shared.global [%0], [%1], 16;" :: "r"(s), "l"(g));
}
__device__ __forceinline__ void cp_commit() {
    asm volatile("cp.async.commit_group;" ::: "memory");
}
__device__ __forceinline__ void cp_wait1() {
    asm volatile("cp.async.wait_group 1;" ::: "memory");
}
__device__ __forceinline__ void ldsm4(uint32_t* r, uint32_t addr) {
    asm volatile("ldmatrix.sync.aligned.m8n8.x4.shared.b16 {%0,%1,%2,%3}, [%4];"
        : "=r"(r[0]), "=r"(r[1]), "=r"(r[2]), "=r"(r[3]) : "r"(addr));
}
__device__ __forceinline__ void mma_tf32(float* c, const uint32_t* a, const uint32_t* b) {
    asm volatile(
        "mma.sync.aligned.m16n8k8.row.col.f32.tf32.tf32.f32 "
        "{%0,%1,%2,%3}, {%4,%5,%6,%7}, {%8,%9}, {%0,%1,%2,%3};"
        : "+f"(c[0]), "+f"(c[1]), "+f"(c[2]), "+f"(c[3])
        : "r"(a[0]), "r"(a[1]), "r"(a[2]), "r"(a[3]), "r"(b[0]), "r"(b[1]));
}

// ---------------- mma.sync tf32 GEMM, 3-stage cp.async + ldmatrix, 2 CTA/SM ------
#define BM 128
#define BN 128
#define BK 32
#define LDT (BK + 4)            // 36 floats
#define STAGES 3
#define KTILES (CDIM / BK)      // 24
#define GTHR 256
#define GEMM_SMEM (STAGES * (BM + BN) * LDT * 4)   // 110592 B

template <int ROUND>
__global__ void __launch_bounds__(GTHR, 2)
gemm_mma_kernel(const float* __restrict__ A, int lda,
                const float* __restrict__ Bw, size_t bstride,
                float* __restrict__ C, int ldc,
                const float* __restrict__ alpha, const float* __restrict__ beta,
                const float* __restrict__ p1, const float* __restrict__ p2) {
    extern __shared__ float smem[];
    float* As = smem;                                // [STAGES][BM][LDT]
    float* Bs = smem + STAGES * BM * LDT;            // [STAGES][BN][LDT]

    const int tid = threadIdx.x, lane = tid & 31, wid = tid >> 5;
    const int gid = lane >> 2, tig = lane & 3;
    const int wm = (wid & 3) * 32;        // 4 warps in M -> 32 rows each
    const int wn = (wid >> 2) * 64;       // 2 warps in N -> 64 cols each
    const int bm0 = blockIdx.y * BM, bn0 = blockIdx.x * BN;

    // ---- loader mapping: 128 rows x 32 floats each for A and B ----
    const int lrow = tid >> 1, lcol = (tid & 1) * 16;
    const float* Ag = A + (size_t)(bm0 + lrow) * lda + lcol;
    const float* Bg = Bw + (size_t)(bm0 >> 12) * bstride + (size_t)(bn0 + lrow) * CDIM + lcol;
    const uint32_t aS0 = smem_u32(As) + (uint32_t)(lrow * LDT + lcol) * 4;
    const uint32_t bS0 = smem_u32(Bs) + (uint32_t)(lrow * LDT + lcol) * 4;

    // ---- ldmatrix per-lane addresses ----
    const int mi = lane >> 3, mr = lane & 7;
    uint32_t aLd[2];
#pragma unroll
    for (int mf = 0; mf < 2; mf++)
        aLd[mf] = (uint32_t)(((wm + mf * 16 + (mi & 1) * 8 + mr) * LDT + (mi >> 1) * 4) * 4);
    uint32_t bLd[4];
#pragma unroll
    for (int p = 0; p < 4; p++)
        bLd[p] = (uint32_t)(((wn + p * 16 + (mi >> 1) * 8 + mr) * LDT + (mi & 1) * 4) * 4);
    const uint32_t aBase = smem_u32(As), bBase = smem_u32(Bs);

    float acc[2][8][4];
#pragma unroll
    for (int i = 0; i < 2; i++)
#pragma unroll
        for (int j = 0; j < 8; j++)
#pragma unroll
            for (int r = 0; r < 4; r++) acc[i][j][r] = 0.f;

    auto load_stage = [&](int s, int kt) {
        const float* ag = Ag + kt * BK;
        const float* bg = Bg + kt * BK;
        uint32_t ad = aS0 + (uint32_t)(s * BM * LDT) * 4;
        uint32_t bd = bS0 + (uint32_t)(s * BN * LDT) * 4;
#pragma unroll
        for (int j = 0; j < 4; j++) cpasync16(ad + j * 16, ag + j * 4);
#pragma unroll
        for (int j = 0; j < 4; j++) cpasync16(bd + j * 16, bg + j * 4);
    };

    auto compute = [&](int s) {
        const uint32_t aSt = aBase + (uint32_t)(s * BM * LDT) * 4;
        const uint32_t bSt = bBase + (uint32_t)(s * BN * LDT) * 4;
#pragma unroll
        for (int ks = 0; ks < 4; ks++) {
            const uint32_t ko = (uint32_t)(ks * 8 * 4);
            uint32_t af[2][4], bf[8][2];
#pragma unroll
            for (int mf = 0; mf < 2; mf++)
                ldsm4(af[mf], aSt + aLd[mf] + ko);
#pragma unroll
            for (int p = 0; p < 4; p++) {
                uint32_t r[4];
                ldsm4(r, bSt + bLd[p] + ko);
                bf[2 * p][0] = r[0]; bf[2 * p][1] = r[1];
                bf[2 * p + 1][0] = r[2]; bf[2 * p + 1][1] = r[3];
            }
#pragma unroll
            for (int mf = 0; mf < 2; mf++)
#pragma unroll
                for (int nf = 0; nf < 8; nf++)
                    mma_tf32(acc[mf][nf], af[mf], bf[nf]);
        }
    };

    load_stage(0, 0); cp_commit();
    load_stage(1, 1); cp_commit();
    cp_wait1();
    __syncthreads();

    for (int kt = 0; kt < KTILES; kt++) {
        int s = kt % STAGES;
        if (kt + 2 < KTILES) load_stage((kt + 2) % STAGES, kt + 2);
        cp_commit();
        compute(s);
        cp_wait1();
        __syncthreads();
    }

    // ---- epilogue ----
#pragma unroll
    for (int mf = 0; mf < 2; mf++) {
        int r0 = bm0 + wm + mf * 16 + gid;
        float al0 = __ldg(alpha + r0), be0 = __ldg(beta + r0);
        float al1 = __ldg(alpha + r0 + 8), be1 = __ldg(beta + r0 + 8);
        float* crow0 = C + (size_t)r0 * ldc;
        float* crow1 = C + (size_t)(r0 + 8) * ldc;
#pragma unroll
        for (int nf = 0; nf < 8; nf++) {
            int c = bn0 + wn + nf * 8 + tig * 2;
            float q10 = __ldg(p1 + c), q11 = __ldg(p1 + c + 1);
            float q20 = __ldg(p2 + c), q21 = __ldg(p2 + c + 1);
            float v0 = al0 * acc[mf][nf][0] + be0 * q10 + q20;
            float v1 = al0 * acc[mf][nf][1] + be0 * q11 + q21;
            float v2 = al1 * acc[mf][nf][2] + be1 * q10 + q20;
            float v3 = al1 * acc[mf][nf][3] + be1 * q11 + q21;
            if (ROUND) { v0 = tf32f(v0); v1 = tf32f(v1); v2 = tf32f(v2); v3 = tf32f(v3); }
            *(float2*)(crow0 + c) = make_float2(v0, v1);
            *(float2*)(crow1 + c) = make_float2(v2, v3);
        }
    }
}

// ---------------- prep kernels ----------------
__global__ void zaux_kernel(float* __restrict__ s1, float* __restrict__ s2,
                            float* __restrict__ kv) {
    int i = blockIdx.x * 1024 + threadIdx.x;
    if (i < QKVCOLS) { s1[i] = 0.f; s2[i] = 0.f; }
    if (i < BATCH * EDIM) kv[i] = 0.f;
}

__global__ void wqkvT_cs_kernel(const float* __restrict__ w, const float* __restrict__ g,
                                const float* __restrict__ b, float* __restrict__ wt,
                                float* __restrict__ s1, float* __restrict__ s2) {
    __shared__ float tg[32][33], tb[32][33];
    __shared__ float rg[8][33], rb[8][33];
    int nb = blockIdx.x * 32, kb = blockIdx.y * 32;
    int tx = threadIdx.x, ty = threadIdx.y;
#pragma unroll
    for (int i = 0; i < 4; i++) {
        int k = kb + ty + i * 8;
        float wv = w[(size_t)k * QKVCOLS + nb + tx];
        tg[ty + i * 8][tx] = g[k] * wv;
        tb[ty + i * 8][tx] = b[k] * wv;
    }
    __syncthreads();
#pragma unroll
    for (int i = 0; i < 4; i++) {
        int n = nb + ty + i * 8;
        wt[(size_t)n * CDIM + kb + tx] = tf32f(tg[tx][ty + i * 8]);
    }
    float sg = 0.f, sb = 0.f;
#pragma unroll
    for (int i = 0; i < 4; i++) { sg += tg[ty + i * 8][tx]; sb += tb[ty + i * 8][tx]; }
    rg[ty][tx] = sg; rb[ty][tx] = sb;
    __syncthreads();
    if (ty == 0) {
        float ag = 0.f, ab = 0.f;
#pragma unroll
        for (int t = 0; t < 8; t++) { ag += rg[t][tx]; ab += rb[t][tx]; }
        atomicAdd(&s1[nb + tx], ag);
        atomicAdd(&s2[nb + tx], ab);
    }
}

__global__ void ln_stats_round_kernel(const float* __restrict__ x, float* __restrict__ xr,
                                      float* __restrict__ alpha, float* __restrict__ beta) {
    int m = blockIdx.x * 8 + (threadIdx.x >> 5);
    int lane = threadIdx.x & 31;
    const float* row = x + (size_t)m * CDIM;
    float* orow = xr + (size_t)m * CDIM;
    float v[24], s = 0.f;
#pragma unroll
    for (int i = 0; i < 24; i++) { v[i] = row[lane + 32 * i]; s += v[i]; }
#pragma unroll
    for (int i = 0; i < 24; i++) orow[lane + 32 * i] = tf32f(v[i]);
    s = wsum(s);
    float mean = s * (1.0f / CDIM);
    float ss = 0.f;
#pragma unroll
    for (int i = 0; i < 24; i++) { float d = v[i] - mean; ss += d * d; }
    ss = wsum(ss);
    if (lane == 0) {
        float rs = rsqrtf(ss * (1.0f / CDIM) + 1e-5f);
        alpha[m] = rs;
        beta[m] = -mean * rs;
    }
}

__global__ void wprojT_kernel(const float* __restrict__ wp, const float* __restrict__ g2,
                              const float* __restrict__ kv, float* __restrict__ wbt) {
    __shared__ float t[32][33];
    int nb = blockIdx.x * 32, eb = blockIdx.y * 32, b = blockIdx.z;
    int tx = threadIdx.x, ty = threadIdx.y;
#pragma unroll
    for (int i = 0; i < 4; i++) {
        int e = eb + ty + i * 8;
        t[ty + i * 8][tx] = kv[b * EDIM + e] * g2[e] * wp[(size_t)e * CDIM + nb + tx];
    }
    __syncthreads();
#pragma unroll
    for (int i = 0; i < 4; i++) {
        int n = nb + ty + i * 8;
        wbt[((size_t)b * EDIM + n) * EDIM + eb + tx] = tf32f(t[tx][ty + i * 8]);
    }
}

__global__ void colsum2_kernel(const float* __restrict__ wp, const float* __restrict__ g2,
                               const float* __restrict__ b2, float* __restrict__ t1,
                               float* __restrict__ t2) {
    int n = blockIdx.x * 256 + threadIdx.x;
    float a = 0.f, c = 0.f;
    for (int e = 0; e < EDIM; e++) {
        float wv = wp[(size_t)e * CDIM + n];
        a += g2[e] * wv; c += b2[e] * wv;
    }
    t1[n] = a; t2[n] = c;
}

// ---------------- stats kernels ----------------
__global__ void knorm_kernel(const float* __restrict__ qkv, float* __restrict__ invnk) {
    int m = blockIdx.x * 8 + (threadIdx.x >> 5);
    int lane = threadIdx.x & 31;
    const float* row = qkv + (size_t)m * QKVCOLS + EDIM;
    float ss = 0.f;
#pragma unroll
    for (int i = 0; i < 24; i++) { float t = row[lane + 32 * i]; ss += t * t; }
    ss = wsum(ss);
    if (lane == 0) invnk[m] = 1.0f / fmaxf(sqrtf(ss), 1e-12f);
}

__global__ void kv_acc_kernel(const float* __restrict__ qkv,
                              const float* __restrict__ invnk,
                              float* __restrict__ kv) {
    int b = blockIdx.y, chunk = blockIdx.x, tid = threadIdx.x;
    float a0 = 0.f, a1 = 0.f, a2 = 0.f;
    int m0 = b * SEQ + chunk * 128;
    for (int t = 0; t < 128; t++) {
        size_t base = (size_t)(m0 + t) * QKVCOLS;
        float inv = __ldg(invnk + m0 + t);
        const float* kr = qkv + base + EDIM;
        const float* vr = qkv + base + 2 * EDIM;
        a0 += kr[tid] * inv * vr[tid];
        a1 += kr[tid + 256] * inv * vr[tid + 256];
        a2 += kr[tid + 512] * inv * vr[tid + 512];
    }
    atomicAdd(&kv[b * EDIM + tid], a0);
    atomicAdd(&kv[b * EDIM + tid + 256], a1);
    atomicAdd(&kv[b * EDIM + tid + 512], a2);
}

__global__ void qstats_kernel(const float* __restrict__ qkv, const float* __restrict__ kv,
                              float* __restrict__ alpha, float* __restrict__ beta) {
    int m = blockIdx.x * 8 + (threadIdx.x >> 5);
    int lane = threadIdx.x & 31;
    const float* qr = qkv + (size_t)m * QKVCOLS;
    const float* kvr = kv + (m >> 12) * EDIM;
    float sq = 0.f, s1 = 0.f, s2 = 0.f;
#pragma unroll
    for (int i = 0; i < 24; i++) {
        int e = lane + 32 * i;
        float q = qr[e], c = kvr[e];
        sq += q * q;
        float a = q * c;
        s1 += a; s2 += a * a;
    }
    sq = wsum(sq); s1 = wsum(s1); s2 = wsum(s2);
    if (lane == 0) {
        float inv = 1.0f / fmaxf(sqrtf(sq), 1e-12f);
        float mean = s1 * inv * (1.0f / EDIM);
        float msq = s2 * inv * inv * (1.0f / EDIM);
        float var = fmaxf(msq - mean * mean, 0.f);
        float rs2 = rsqrtf(var + 1e-5f);
        alpha[m] = rs2 * inv;
        beta[m] = -mean * rs2;
    }
}

// ---------------- launcher ----------------
extern "C" void kernel_launch(void* const* d_in, const int* in_sizes, int n_in,
                              void* d_out, int out_size) {
    (void)in_sizes; (void)n_in; (void)out_size;
    const float* x      = (const float*)d_in[0];
    const float* w_qkv  = (const float*)d_in[1];
    const float* w_proj = (const float*)d_in[2];
    const float* g_in   = (const float*)d_in[3];
    const float* b_in   = (const float*)d_in[4];
    const float* g_out  = (const float*)d_in[5];
    const float* b_out  = (const float*)d_in[6];
    float* out = (float*)d_out;

    float *qkv, *xr, *wgt, *wbt, *s1, *s2, *t1, *t2, *a1, *be1, *a2, *be2, *invnk, *kv;
    cudaGetSymbolAddress((void**)&qkv, g_qkv);
    cudaGetSymbolAddress((void**)&xr, g_xr);
    cudaGetSymbolAddress((void**)&wgt, g_wgt);
    cudaGetSymbolAddress((void**)&wbt, g_wbt);
    cudaGetSymbolAddress((void**)&s1, g_s1);
    cudaGetSymbolAddress((void**)&s2, g_s2);
    cudaGetSymbolAddress((void**)&t1, g_t1);
    cudaGetSymbolAddress((void**)&t2, g_t2);
    cudaGetSymbolAddress((void**)&a1, g_alpha1);
    cudaGetSymbolAddress((void**)&be1, g_beta1);
    cudaGetSymbolAddress((void**)&a2, g_alpha2);
    cudaGetSymbolAddress((void**)&be2, g_beta2);
    cudaGetSymbolAddress((void**)&invnk, g_invnk);
    cudaGetSymbolAddress((void**)&kv, g_kv);

    cudaFuncSetAttribute(gemm_mma_kernel<1>, cudaFuncAttributeMaxDynamicSharedMemorySize, GEMM_SMEM);
    cudaFuncSetAttribute(gemm_mma_kernel<0>, cudaFuncAttributeMaxDynamicSharedMemorySize, GEMM_SMEM);

    // (1) zero atomic targets
    zaux_kernel<<<(BATCH * EDIM + 1023) / 1024, 1024>>>(s1, s2, kv);
    // (2) fused weight transpose + colsums
    wqkvT_cs_kernel<<<dim3(QKVCOLS / 32, CDIM / 32), dim3(32, 8)>>>(w_qkv, g_in, b_in, wgt, s1, s2);
    // (3) fused LN stats + tf32 rounding of x
    ln_stats_round_kernel<<<MTOK / 8, 256>>>(x, xr, a1, be1);
    // (4) GEMM1 (ncu capture slot)
    gemm_mma_kernel<1><<<dim3(QKVCOLS / BN, MTOK / BM), GTHR, GEMM_SMEM>>>(
        xr, CDIM, wgt, 0, qkv, QKVCOLS, a1, be1, s1, s2);
    // (5-7) kv pipeline
    knorm_kernel<<<MTOK / 8, 256>>>(qkv, invnk);
    kv_acc_kernel<<<dim3(SEQ / 128, BATCH), 256>>>(qkv, invnk, kv);
    qstats_kernel<<<MTOK / 8, 256>>>(qkv, kv, a2, be2);
    // (8-9) GEMM2 weights
    wprojT_kernel<<<dim3(CDIM / 32, EDIM / 32, BATCH), dim3(32, 8)>>>(w_proj, g_out, kv, wbt);
    colsum2_kernel<<<CDIM / 256, 256>>>(w_proj, g_out, b_out, t1, t2);
    // (10) GEMM2
    gemm_mma_kernel<0><<<dim3(CDIM / BN, MTOK / BM), GTHR, GEMM_SMEM>>>(
        qkv, QKVCOLS, wbt, (size_t)EDIM * EDIM, out, CDIM, a2, be2, t1, t2);
}